// round 6
// baseline (speedup 1.0000x reference)
#include <cuda_runtime.h>
#include <math.h>

#define N_NODES 50000
#define N_EDGES 400000
#define HEADS 8
#define HID 32
#define F 256            // HEADS*HID
#define NEG 0.2f

// ---------------- scratch (device globals: allocation-free) ----------------
__device__ float g_h[N_NODES * F];        // X @ W (pre-attention features)
__device__ float g_x[N_NODES * F];        // layer output
__device__ float g_asrc[N_NODES * HEADS];
__device__ float g_adst[N_NODES * HEADS];
__device__ float g_p[N_NODES * 64];       // [P_a | P_b] node projections
__device__ float g_wcat[256 * 64];        // [Wp1_a | Wp1_b] packed
__device__ int   g_cnt[N_NODES];
__device__ int   g_off[N_NODES + 1];
__device__ int   g_fill[N_NODES];
__device__ int   g_bsum[256];
__device__ int   g_csrc[N_EDGES];

__device__ __forceinline__ float leaky(float x) { return x > 0.f ? x : NEG * x; }

__device__ __forceinline__ unsigned f2tf(float f) {
    unsigned r;
    asm("cvt.rna.tf32.f32 %0, %1;" : "=r"(r) : "f"(f));
    return r;
}

__device__ __forceinline__ void mma8(float* c,
    unsigned a0, unsigned a1, unsigned a2, unsigned a3,
    unsigned b0, unsigned b1)
{
    asm volatile(
        "mma.sync.aligned.m16n8k8.row.col.f32.tf32.tf32.f32 "
        "{%0,%1,%2,%3}, {%4,%5,%6,%7}, {%8,%9}, {%0,%1,%2,%3};"
        : "+f"(c[0]), "+f"(c[1]), "+f"(c[2]), "+f"(c[3])
        : "r"(a0), "r"(a1), "r"(a2), "r"(a3), "r"(b0), "r"(b1));
}

// ---------------- SGEMM: C[M x N] = A[M x K] @ B[K x N] -------------------
// 128x64 tile, BK=16, 256 threads, 8x4 micro-tile. (fp32 SIMT — round-4 ver.)
// Optional fused epilogue: per-row attention dots for the 2 heads in this tile.
__global__ __launch_bounds__(256) void sgemm_kernel(
    const float* __restrict__ A, const float* __restrict__ B,
    float* __restrict__ C, int M, int K, int ldb, int ldc,
    const float* __restrict__ a_src, const float* __restrict__ a_dst)
{
    __shared__ float As[16][128];
    __shared__ float Bs[16][64];
    __shared__ float sAs[64], sAd[64];
    const int tid = threadIdx.x;
    const int tx = tid & 15;
    const int ty = tid >> 4;
    const int m0 = blockIdx.x * 128;
    const int n0 = blockIdx.y * 64;

    if (a_src != nullptr && tid < 64) {
        sAs[tid] = a_src[n0 + tid];
        sAd[tid] = a_dst[n0 + tid];
    }

    float acc[8][4];
#pragma unroll
    for (int i = 0; i < 8; ++i)
#pragma unroll
        for (int j = 0; j < 4; ++j) acc[i][j] = 0.f;

    for (int k0 = 0; k0 < K; k0 += 16) {
#pragma unroll
        for (int jj = 0; jj < 2; ++jj) {
            int f = tid + jj * 256;
            int m = f >> 2;
            int kq = (f & 3) * 4;
            float4 v = make_float4(0.f, 0.f, 0.f, 0.f);
            if (m0 + m < M)
                v = *(const float4*)&A[(size_t)(m0 + m) * K + k0 + kq];
            As[kq + 0][m] = v.x; As[kq + 1][m] = v.y;
            As[kq + 2][m] = v.z; As[kq + 3][m] = v.w;
        }
        {
            int kk = tid >> 4;
            int nq = (tid & 15) * 4;
            *(float4*)&Bs[kk][nq] = *(const float4*)&B[(size_t)(k0 + kk) * ldb + n0 + nq];
        }
        __syncthreads();
#pragma unroll
        for (int kk = 0; kk < 16; ++kk) {
            float4 b4 = *(float4*)&Bs[kk][tx * 4];
            float4 a0 = *(float4*)&As[kk][ty * 8];
            float4 a1 = *(float4*)&As[kk][ty * 8 + 4];
            float a[8] = {a0.x, a0.y, a0.z, a0.w, a1.x, a1.y, a1.z, a1.w};
#pragma unroll
            for (int i = 0; i < 8; ++i) {
                acc[i][0] += a[i] * b4.x; acc[i][1] += a[i] * b4.y;
                acc[i][2] += a[i] * b4.z; acc[i][3] += a[i] * b4.w;
            }
        }
        __syncthreads();
    }
#pragma unroll
    for (int i = 0; i < 8; ++i) {
        int m = m0 + ty * 8 + i;
        if (m < M)
            *(float4*)&C[(size_t)m * ldc + n0 + tx * 4] =
                make_float4(acc[i][0], acc[i][1], acc[i][2], acc[i][3]);
    }
    if (a_src != nullptr) {
        float4 wa = *(float4*)&sAs[tx * 4];
        float4 wd = *(float4*)&sAd[tx * 4];
#pragma unroll
        for (int i = 0; i < 8; ++i) {
            float ps = acc[i][0] * wa.x + acc[i][1] * wa.y + acc[i][2] * wa.z + acc[i][3] * wa.w;
            float pd = acc[i][0] * wd.x + acc[i][1] * wd.y + acc[i][2] * wd.z + acc[i][3] * wd.w;
            ps += __shfl_down_sync(0xffffffffu, ps, 4, 8);
            ps += __shfl_down_sync(0xffffffffu, ps, 2, 8);
            ps += __shfl_down_sync(0xffffffffu, ps, 1, 8);
            pd += __shfl_down_sync(0xffffffffu, pd, 4, 8);
            pd += __shfl_down_sync(0xffffffffu, pd, 2, 8);
            pd += __shfl_down_sync(0xffffffffu, pd, 1, 8);
            int m = m0 + ty * 8 + i;
            if ((tx & 7) == 0 && m < M) {
                int head = (n0 >> 5) + (tx >> 3);
                g_asrc[m * 8 + head] = ps;
                g_adst[m * 8 + head] = pd;
            }
        }
    }
}

// ---------------- CSR build ----------------
__global__ __launch_bounds__(256) void zero_cnt_kernel()
{
    int i = blockIdx.x * blockDim.x + threadIdx.x;
    if (i < N_NODES) g_cnt[i] = 0;
}
__global__ __launch_bounds__(256) void count_kernel(const int* __restrict__ ei)
{
    int e = blockIdx.x * blockDim.x + threadIdx.x;
    if (e < N_EDGES) atomicAdd(&g_cnt[ei[N_EDGES + e]], 1);
}
__global__ __launch_bounds__(256) void scan1_kernel()
{
    __shared__ int sh[256];
    int i = blockIdx.x * 256 + threadIdx.x;
    int v = (i < N_NODES) ? g_cnt[i] : 0;
    sh[threadIdx.x] = v;
    __syncthreads();
#pragma unroll
    for (int off = 1; off < 256; off <<= 1) {
        int t = 0;
        if (threadIdx.x >= off) t = sh[threadIdx.x - off];
        __syncthreads();
        if (threadIdx.x >= off) sh[threadIdx.x] += t;
        __syncthreads();
    }
    if (i < N_NODES) g_off[i + 1] = sh[threadIdx.x];
    if (threadIdx.x == 255) g_bsum[blockIdx.x] = sh[255];
    if (i == 0) g_off[0] = 0;
}
__global__ __launch_bounds__(256) void scan2_kernel(int nblocks)
{
    __shared__ int sh[256];
    int t = threadIdx.x;
    int v = (t < nblocks) ? g_bsum[t] : 0;
    sh[t] = v;
    __syncthreads();
#pragma unroll
    for (int off = 1; off < 256; off <<= 1) {
        int u = 0;
        if (t >= off) u = sh[t - off];
        __syncthreads();
        if (t >= off) sh[t] += u;
        __syncthreads();
    }
    if (t < nblocks) g_bsum[t] = sh[t] - v;    // exclusive
}
__global__ __launch_bounds__(256) void scan3_kernel()
{
    int i = blockIdx.x * 256 + threadIdx.x;
    if (i < N_NODES) {
        int v = g_off[i + 1] + g_bsum[blockIdx.x];
        g_off[i + 1] = v;
        if (i + 1 < N_NODES) g_fill[i + 1] = v;   // fill cursor = final offset
        if (i == 0) g_fill[0] = 0;
    }
}
__global__ __launch_bounds__(256) void scatter_kernel(const int* __restrict__ ei)
{
    int e = blockIdx.x * blockDim.x + threadIdx.x;
    if (e >= N_EDGES) return;
    int s = ei[e], d = ei[N_EDGES + e];
    int pos = atomicAdd(&g_fill[d], 1);
    g_csrc[pos] = s;
}

// -------- gather attention: one warp per node, fused softmax+agg+relu ------
// Edge srcs batch-loaded (coalesced) and body unrolled x2 for MLP.
__global__ __launch_bounds__(256) void gat_gather_kernel(const float* __restrict__ b)
{
    const int warp = threadIdx.x >> 5, lane = threadIdx.x & 31;
    const int n = blockIdx.x * 8 + warp;
    if (n >= N_NODES) return;
    const unsigned FULL = 0xffffffffu;
    const int h0 = lane >> 3, h1 = 4 + (lane >> 3);

    float myasrc = 0.f, myadst = 0.f;
    if (lane < 8) {
        myasrc = g_asrc[n * 8 + lane];
        myadst = g_adst[n * 8 + lane];
    }
    float4 acc0 = make_float4(0.f, 0.f, 0.f, 0.f);
    float4 acc1 = make_float4(0.f, 0.f, 0.f, 0.f);
    float denom = 0.f;

    const int beg = g_off[n], end = g_off[n + 1];
    for (int i = beg; i < end; i += 32) {
        int rem = end - i;
        int nb = rem < 32 ? rem : 32;
        int sb = 0;
        if (lane < nb) sb = g_csrc[i + lane];

        int j = 0;
        for (; j + 2 <= nb; j += 2) {
            int s0 = __shfl_sync(FULL, sb, j);
            int s1 = __shfl_sync(FULL, sb, j + 1);
            float w0 = 0.f, w1 = 0.f;
            if (lane < 8) {
                w0 = expf(leaky(g_asrc[s0 * 8 + lane] + myadst));
                w1 = expf(leaky(g_asrc[s1 * 8 + lane] + myadst));
                denom += w0 + w1;
            }
            float a00 = __shfl_sync(FULL, w0, h0);
            float a01 = __shfl_sync(FULL, w0, h1);
            float a10 = __shfl_sync(FULL, w1, h0);
            float a11 = __shfl_sync(FULL, w1, h1);
            float4 u0 = *(const float4*)&g_h[(size_t)s0 * 256 + lane * 4];
            float4 u1 = *(const float4*)&g_h[(size_t)s0 * 256 + 128 + lane * 4];
            float4 v0 = *(const float4*)&g_h[(size_t)s1 * 256 + lane * 4];
            float4 v1 = *(const float4*)&g_h[(size_t)s1 * 256 + 128 + lane * 4];
            acc0.x += a00 * u0.x + a10 * v0.x;
            acc0.y += a00 * u0.y + a10 * v0.y;
            acc0.z += a00 * u0.z + a10 * v0.z;
            acc0.w += a00 * u0.w + a10 * v0.w;
            acc1.x += a01 * u1.x + a11 * v1.x;
            acc1.y += a01 * u1.y + a11 * v1.y;
            acc1.z += a01 * u1.z + a11 * v1.z;
            acc1.w += a01 * u1.w + a11 * v1.w;
        }
        if (j < nb) {
            int s0 = __shfl_sync(FULL, sb, j);
            float w0 = 0.f;
            if (lane < 8) {
                w0 = expf(leaky(g_asrc[s0 * 8 + lane] + myadst));
                denom += w0;
            }
            float a00 = __shfl_sync(FULL, w0, h0);
            float a01 = __shfl_sync(FULL, w0, h1);
            float4 u0 = *(const float4*)&g_h[(size_t)s0 * 256 + lane * 4];
            float4 u1 = *(const float4*)&g_h[(size_t)s0 * 256 + 128 + lane * 4];
            acc0.x += a00 * u0.x; acc0.y += a00 * u0.y;
            acc0.z += a00 * u0.z; acc0.w += a00 * u0.w;
            acc1.x += a01 * u1.x; acc1.y += a01 * u1.y;
            acc1.z += a01 * u1.z; acc1.w += a01 * u1.w;
        }
    }
    // self loop
    {
        float w = 0.f;
        if (lane < 8) {
            w = expf(leaky(myasrc + myadst));
            denom += w;
        }
        float al0 = __shfl_sync(FULL, w, h0);
        float al1 = __shfl_sync(FULL, w, h1);
        float4 v0 = *(const float4*)&g_h[(size_t)n * 256 + lane * 4];
        float4 v1 = *(const float4*)&g_h[(size_t)n * 256 + 128 + lane * 4];
        acc0.x += al0 * v0.x; acc0.y += al0 * v0.y;
        acc0.z += al0 * v0.z; acc0.w += al0 * v0.w;
        acc1.x += al1 * v1.x; acc1.y += al1 * v1.y;
        acc1.z += al1 * v1.z; acc1.w += al1 * v1.w;
    }
    float inv0 = 1.f / __shfl_sync(FULL, denom, h0);
    float inv1 = 1.f / __shfl_sync(FULL, denom, h1);
    float4 bb0 = *(const float4*)&b[lane * 4];
    float4 bb1 = *(const float4*)&b[128 + lane * 4];
    float4 o0, o1;
    o0.x = fmaxf(acc0.x * inv0 + bb0.x, 0.f);
    o0.y = fmaxf(acc0.y * inv0 + bb0.y, 0.f);
    o0.z = fmaxf(acc0.z * inv0 + bb0.z, 0.f);
    o0.w = fmaxf(acc0.w * inv0 + bb0.w, 0.f);
    o1.x = fmaxf(acc1.x * inv1 + bb1.x, 0.f);
    o1.y = fmaxf(acc1.y * inv1 + bb1.y, 0.f);
    o1.z = fmaxf(acc1.z * inv1 + bb1.z, 0.f);
    o1.w = fmaxf(acc1.w * inv1 + bb1.w, 0.f);
    *(float4*)&g_x[(size_t)n * 256 + lane * 4] = o0;
    *(float4*)&g_x[(size_t)n * 256 + 128 + lane * 4] = o1;
}

// ---------------- pack Wcat = [Wp1_a | Wp1_b] : [256 x 64] ----------------
__global__ __launch_bounds__(256) void pack_wcat_kernel(const float* __restrict__ Wp1)
{
    int i = blockIdx.x * blockDim.x + threadIdx.x;
    if (i >= 256 * 64) return;
    int k = i >> 6, j = i & 63;
    g_wcat[i] = (j < 32) ? Wp1[k * 32 + j] : Wp1[(256 + k) * 32 + (j - 32)];
}

// ------- edge predictor: tf32-MMA edge-MLP + exact fp32 combine ------------
// 64 edges/block, 128 threads (4 warps); warp handles rows wrp*16..+15.
// Weight buffers packed once; layer staging is warp-private (only syncwarp).
__global__ __launch_bounds__(128) void edge_pred_kernel(
    const int* __restrict__ ei, const float* __restrict__ edge_attr,
    const float* __restrict__ Wm1, const float* __restrict__ bm1,
    const float* __restrict__ Wm2, const float* __restrict__ bm2,
    const float* __restrict__ Wp1, const float* __restrict__ bp1,
    const float* __restrict__ Wp2, const float* __restrict__ bp2,
    float* __restrict__ out)
{
    __shared__ unsigned sEA[64 * 33];                 // layer input staging (tf32)
    __shared__ unsigned sT[64 * 33];                  // layer output staging (tf32)
    __shared__ __align__(8) unsigned sW1[1056], sW2[1056], sW3[1056];
    __shared__ int sRow[64], sCol[64];

    const int tid = threadIdx.x;
    const int lane = tid & 31;
    const int wrp = tid >> 5;
    const int tig = lane & 3;
    const int grp = lane >> 2;
    const int e0 = blockIdx.x * 64;
    const int row0 = wrp * 16 + grp;

    if (tid < 64) {
        sRow[tid] = ei[e0 + tid];
        sCol[tid] = ei[N_EDGES + e0 + tid];
    }
    // pack the three 32x32 weights (col-fragment pairs)
    for (int i = tid; i < 1024; i += 128) {
        int r = i >> 5, c = i & 31;
        int ks = r >> 3, kk = r & 7;
        int idx = (((ks * 4) + (kk & 3)) * 33 + c) * 2 + (kk >> 2);
        sW1[idx] = f2tf(Wm1[i]);
        sW2[idx] = f2tf(Wm2[i]);
        sW3[idx] = f2tf(Wp1[512 * 32 + i]);
    }
    // stage EA as tf32
    for (int f = tid; f < 64 * 8; f += 128) {
        int e = f >> 3, q = f & 7;
        float4 v = *(const float4*)&edge_attr[(size_t)(e0 + e) * 32 + q * 4];
        unsigned* p = &sEA[e * 33 + q * 4];
        p[0] = f2tf(v.x); p[1] = f2tf(v.y); p[2] = f2tf(v.z); p[3] = f2tf(v.w);
    }
    __syncthreads();

    // ---- layer 1: T = relu(EA @ Wm1 + bm1) ----
    {
        float em[4][4];
#pragma unroll
        for (int nt = 0; nt < 4; ++nt)
#pragma unroll
            for (int j = 0; j < 4; ++j) em[nt][j] = 0.f;
#pragma unroll
        for (int ks = 0; ks < 4; ++ks) {
            int k = ks * 8 + tig;
            unsigned a0 = sEA[row0 * 33 + k];
            unsigned a1 = sEA[(row0 + 8) * 33 + k];
            unsigned a2 = sEA[row0 * 33 + k + 4];
            unsigned a3 = sEA[(row0 + 8) * 33 + k + 4];
#pragma unroll
            for (int nt = 0; nt < 4; ++nt) {
                uint2 b = *(uint2*)&sW1[((ks * 4 + tig) * 33 + nt * 8 + grp) * 2];
                mma8(em[nt], a0, a1, a2, a3, b.x, b.y);
            }
        }
#pragma unroll
        for (int nt = 0; nt < 4; ++nt) {
            int j0 = nt * 8 + 2 * tig, j1 = j0 + 1;
            float b0 = bm1[j0], b1 = bm1[j1];
            float v;
            v = em[nt][0] + b0; sT[row0 * 33 + j0]       = f2tf(v > 0.f ? v : 0.f);
            v = em[nt][1] + b1; sT[row0 * 33 + j1]       = f2tf(v > 0.f ? v : 0.f);
            v = em[nt][2] + b0; sT[(row0 + 8) * 33 + j0] = f2tf(v > 0.f ? v : 0.f);
            v = em[nt][3] + b1; sT[(row0 + 8) * 33 + j1] = f2tf(v > 0.f ? v : 0.f);
        }
    }
    __syncwarp();

    // ---- layer 2: EA = relu(T @ Wm2 + bm2) ----
    {
        float em[4][4];
#pragma unroll
        for (int nt = 0; nt < 4; ++nt)
#pragma unroll
            for (int j = 0; j < 4; ++j) em[nt][j] = 0.f;
#pragma unroll
        for (int ks = 0; ks < 4; ++ks) {
            int k = ks * 8 + tig;
            unsigned a0 = sT[row0 * 33 + k];
            unsigned a1 = sT[(row0 + 8) * 33 + k];
            unsigned a2 = sT[row0 * 33 + k + 4];
            unsigned a3 = sT[(row0 + 8) * 33 + k + 4];
#pragma unroll
            for (int nt = 0; nt < 4; ++nt) {
                uint2 b = *(uint2*)&sW2[((ks * 4 + tig) * 33 + nt * 8 + grp) * 2];
                mma8(em[nt], a0, a1, a2, a3, b.x, b.y);
            }
        }
        __syncwarp();
#pragma unroll
        for (int nt = 0; nt < 4; ++nt) {
            int j0 = nt * 8 + 2 * tig, j1 = j0 + 1;
            float b0 = bm2[j0], b1 = bm2[j1];
            float v;
            v = em[nt][0] + b0; sEA[row0 * 33 + j0]       = f2tf(v > 0.f ? v : 0.f);
            v = em[nt][1] + b1; sEA[row0 * 33 + j1]       = f2tf(v > 0.f ? v : 0.f);
            v = em[nt][2] + b0; sEA[(row0 + 8) * 33 + j0] = f2tf(v > 0.f ? v : 0.f);
            v = em[nt][3] + b1; sEA[(row0 + 8) * 33 + j1] = f2tf(v > 0.f ? v : 0.f);
        }
    }
    __syncwarp();

    // ---- layer 3: P = EMB @ Wp1_c (raw contribution) ----
    float p[4][4];
#pragma unroll
    for (int nt = 0; nt < 4; ++nt)
#pragma unroll
        for (int j = 0; j < 4; ++j) p[nt][j] = 0.f;
#pragma unroll
    for (int ks = 0; ks < 4; ++ks) {
        int k = ks * 8 + tig;
        unsigned a0 = sEA[row0 * 33 + k];
        unsigned a1 = sEA[(row0 + 8) * 33 + k];
        unsigned a2 = sEA[row0 * 33 + k + 4];
        unsigned a3 = sEA[(row0 + 8) * 33 + k + 4];
#pragma unroll
        for (int nt = 0; nt < 4; ++nt) {
            uint2 b = *(uint2*)&sW3[((ks * 4 + tig) * 33 + nt * 8 + grp) * 2];
            mma8(p[nt], a0, a1, a2, a3, b.x, b.y);
        }
    }

    // ---- epilogue: pre = P + P_a[row] + P_b[col] + bp1 ; out = relu@Wp2+bp2
    const int r0n = sRow[row0],     c0n = sCol[row0];
    const int r1n = sRow[row0 + 8], c1n = sCol[row0 + 8];
    float acc_r0 = 0.f, acc_r1 = 0.f;
#pragma unroll
    for (int nt = 0; nt < 4; ++nt) {
        int j0 = nt * 8 + 2 * tig;
        float2 pa0 = *(const float2*)&g_p[(size_t)r0n * 64 + j0];
        float2 pb0 = *(const float2*)&g_p[(size_t)c0n * 64 + 32 + j0];
        float2 pa1 = *(const float2*)&g_p[(size_t)r1n * 64 + j0];
        float2 pb1 = *(const float2*)&g_p[(size_t)c1n * 64 + 32 + j0];
        float b0 = bp1[j0], b1 = bp1[j0 + 1];
        float w0 = Wp2[j0], w1 = Wp2[j0 + 1];
        float h;
        h = p[nt][0] + pa0.x + pb0.x + b0; acc_r0 += (h > 0.f ? h : 0.f) * w0;
        h = p[nt][1] + pa0.y + pb0.y + b1; acc_r0 += (h > 0.f ? h : 0.f) * w1;
        h = p[nt][2] + pa1.x + pb1.x + b0; acc_r1 += (h > 0.f ? h : 0.f) * w0;
        h = p[nt][3] + pa1.y + pb1.y + b1; acc_r1 += (h > 0.f ? h : 0.f) * w1;
    }
    acc_r0 += __shfl_xor_sync(0xffffffffu, acc_r0, 1);
    acc_r0 += __shfl_xor_sync(0xffffffffu, acc_r0, 2);
    acc_r1 += __shfl_xor_sync(0xffffffffu, acc_r1, 1);
    acc_r1 += __shfl_xor_sync(0xffffffffu, acc_r1, 2);
    if (tig == 0) {
        float bias2 = bp2[0];
        out[e0 + row0]     = acc_r0 + bias2;
        out[e0 + row0 + 8] = acc_r1 + bias2;
    }
}

// ---------------- host ----------------
extern "C" void kernel_launch(void* const* d_in, const int* in_sizes, int n_in,
                              void* d_out, int out_size)
{
    const float* x   = (const float*)d_in[0];
    const int*   ei  = (const int*)d_in[1];
    const float* ea  = (const float*)d_in[2];
    const float* W1  = (const float*)d_in[3];
    const float* as1 = (const float*)d_in[4];
    const float* ad1 = (const float*)d_in[5];
    const float* b1  = (const float*)d_in[6];
    const float* W2  = (const float*)d_in[7];
    const float* as2 = (const float*)d_in[8];
    const float* ad2 = (const float*)d_in[9];
    const float* b2  = (const float*)d_in[10];
    const float* Wm1 = (const float*)d_in[11];
    const float* bm1 = (const float*)d_in[12];
    const float* Wm2 = (const float*)d_in[13];
    const float* bm2 = (const float*)d_in[14];
    const float* Wp1 = (const float*)d_in[15];
    const float* bp1 = (const float*)d_in[16];
    const float* Wp2 = (const float*)d_in[17];
    const float* bp2 = (const float*)d_in[18];
    float* out = (float*)d_out;

    float *ph = nullptr, *px = nullptr, *pw = nullptr, *pp = nullptr;
    cudaGetSymbolAddress((void**)&ph, g_h);
    cudaGetSymbolAddress((void**)&px, g_x);
    cudaGetSymbolAddress((void**)&pw, g_wcat);
    cudaGetSymbolAddress((void**)&pp, g_p);

    const int EB  = (N_EDGES + 255) / 256;
    const int NB  = (N_NODES + 255) / 256;
    const int NWB = (N_NODES + 7) / 8;

    // ---- CSR build (once; reused by both layers) ----
    zero_cnt_kernel<<<NB, 256>>>();
    count_kernel<<<EB, 256>>>(ei);
    scan1_kernel<<<NB, 256>>>();
    scan2_kernel<<<1, 256>>>(NB);
    scan3_kernel<<<NB, 256>>>();
    scatter_kernel<<<EB, 256>>>(ei);

    for (int layer = 0; layer < 2; ++layer) {
        const float* X   = layer ? px : x;
        const int    K   = layer ? 256 : 128;
        const float* W   = layer ? W2 : W1;
        const float* as_ = layer ? as2 : as1;
        const float* ad_ = layer ? ad2 : ad1;
        const float* b_  = layer ? b2 : b1;

        sgemm_kernel<<<dim3(391, 4), 256>>>(X, W, ph, N_NODES, K, 256, 256, as_, ad_);
        gat_gather_kernel<<<NWB, 256>>>(b_);
    }
    pack_wcat_kernel<<<64, 256>>>(Wp1);
    sgemm_kernel<<<dim3(391, 1), 256>>>(px, pw, pp, N_NODES, 256, 64, 64,
                                        nullptr, nullptr);
    edge_pred_kernel<<<N_EDGES / 64, 128>>>(ei, ea,
                                            Wm1, bm1, Wm2, bm2,
                                            Wp1, bp1, Wp2, bp2, out);
}

// round 7
// speedup vs baseline: 1.4724x; 1.4724x over previous
#include <cuda_runtime.h>
#include <math.h>

#define N_NODES 50000
#define N_EDGES 400000
#define HEADS 8
#define HID 32
#define F 256            // HEADS*HID
#define NEG 0.2f

// ---------------- scratch (device globals: allocation-free) ----------------
__device__ float g_h[N_NODES * F];        // X @ W (pre-attention features)
__device__ float g_x[N_NODES * F];        // layer output
__device__ float g_asrc[N_NODES * HEADS];
__device__ float g_adst[N_NODES * HEADS];
__device__ float g_p[N_NODES * 64];       // [P_a | P_b] node projections
__device__ float g_wcat[256 * 64];        // [Wp1_a | Wp1_b] packed
__device__ int   g_cnt[N_NODES];
__device__ int   g_off[N_NODES + 1];
__device__ int   g_fill[N_NODES];
__device__ int   g_bsum[256];
__device__ int   g_csrc[N_EDGES];

__device__ __forceinline__ float leaky(float x) { return x > 0.f ? x : NEG * x; }

// ---------------- SGEMM: C[M x N] = A[M x K] @ B[K x N] -------------------
// 128x64 tile, BK=16, 256 threads, 8x4 micro-tile. (round-4 fp32 SIMT)
// Optional fused epilogue: per-row attention dots for the 2 heads in this tile.
__global__ __launch_bounds__(256) void sgemm_kernel(
    const float* __restrict__ A, const float* __restrict__ B,
    float* __restrict__ C, int M, int K, int ldb, int ldc,
    const float* __restrict__ a_src, const float* __restrict__ a_dst)
{
    __shared__ float As[16][128];
    __shared__ float Bs[16][64];
    __shared__ float sAs[64], sAd[64];
    const int tid = threadIdx.x;
    const int tx = tid & 15;
    const int ty = tid >> 4;
    const int m0 = blockIdx.x * 128;
    const int n0 = blockIdx.y * 64;

    if (a_src != nullptr && tid < 64) {
        sAs[tid] = a_src[n0 + tid];
        sAd[tid] = a_dst[n0 + tid];
    }

    float acc[8][4];
#pragma unroll
    for (int i = 0; i < 8; ++i)
#pragma unroll
        for (int j = 0; j < 4; ++j) acc[i][j] = 0.f;

    for (int k0 = 0; k0 < K; k0 += 16) {
#pragma unroll
        for (int jj = 0; jj < 2; ++jj) {
            int f = tid + jj * 256;
            int m = f >> 2;
            int kq = (f & 3) * 4;
            float4 v = make_float4(0.f, 0.f, 0.f, 0.f);
            if (m0 + m < M)
                v = *(const float4*)&A[(size_t)(m0 + m) * K + k0 + kq];
            As[kq + 0][m] = v.x; As[kq + 1][m] = v.y;
            As[kq + 2][m] = v.z; As[kq + 3][m] = v.w;
        }
        {
            int kk = tid >> 4;
            int nq = (tid & 15) * 4;
            *(float4*)&Bs[kk][nq] = *(const float4*)&B[(size_t)(k0 + kk) * ldb + n0 + nq];
        }
        __syncthreads();
#pragma unroll
        for (int kk = 0; kk < 16; ++kk) {
            float4 b4 = *(float4*)&Bs[kk][tx * 4];
            float4 a0 = *(float4*)&As[kk][ty * 8];
            float4 a1 = *(float4*)&As[kk][ty * 8 + 4];
            float a[8] = {a0.x, a0.y, a0.z, a0.w, a1.x, a1.y, a1.z, a1.w};
#pragma unroll
            for (int i = 0; i < 8; ++i) {
                acc[i][0] += a[i] * b4.x; acc[i][1] += a[i] * b4.y;
                acc[i][2] += a[i] * b4.z; acc[i][3] += a[i] * b4.w;
            }
        }
        __syncthreads();
    }
#pragma unroll
    for (int i = 0; i < 8; ++i) {
        int m = m0 + ty * 8 + i;
        if (m < M)
            *(float4*)&C[(size_t)m * ldc + n0 + tx * 4] =
                make_float4(acc[i][0], acc[i][1], acc[i][2], acc[i][3]);
    }
    if (a_src != nullptr) {
        float4 wa = *(float4*)&sAs[tx * 4];
        float4 wd = *(float4*)&sAd[tx * 4];
#pragma unroll
        for (int i = 0; i < 8; ++i) {
            float ps = acc[i][0] * wa.x + acc[i][1] * wa.y + acc[i][2] * wa.z + acc[i][3] * wa.w;
            float pd = acc[i][0] * wd.x + acc[i][1] * wd.y + acc[i][2] * wd.z + acc[i][3] * wd.w;
            ps += __shfl_down_sync(0xffffffffu, ps, 4, 8);
            ps += __shfl_down_sync(0xffffffffu, ps, 2, 8);
            ps += __shfl_down_sync(0xffffffffu, ps, 1, 8);
            pd += __shfl_down_sync(0xffffffffu, pd, 4, 8);
            pd += __shfl_down_sync(0xffffffffu, pd, 2, 8);
            pd += __shfl_down_sync(0xffffffffu, pd, 1, 8);
            int m = m0 + ty * 8 + i;
            if ((tx & 7) == 0 && m < M) {
                int head = (n0 >> 5) + (tx >> 3);
                g_asrc[m * 8 + head] = ps;
                g_adst[m * 8 + head] = pd;
            }
        }
    }
}

// ---------------- CSR build ----------------
__global__ __launch_bounds__(256) void zero_cnt_kernel()
{
    int i = blockIdx.x * blockDim.x + threadIdx.x;
    if (i < N_NODES) g_cnt[i] = 0;
}
__global__ __launch_bounds__(256) void count_kernel(const int* __restrict__ ei)
{
    int e = blockIdx.x * blockDim.x + threadIdx.x;
    if (e < N_EDGES) atomicAdd(&g_cnt[ei[N_EDGES + e]], 1);
}
__global__ __launch_bounds__(256) void scan1_kernel()
{
    __shared__ int sh[256];
    int i = blockIdx.x * 256 + threadIdx.x;
    int v = (i < N_NODES) ? g_cnt[i] : 0;
    sh[threadIdx.x] = v;
    __syncthreads();
#pragma unroll
    for (int off = 1; off < 256; off <<= 1) {
        int t = 0;
        if (threadIdx.x >= off) t = sh[threadIdx.x - off];
        __syncthreads();
        if (threadIdx.x >= off) sh[threadIdx.x] += t;
        __syncthreads();
    }
    if (i < N_NODES) g_off[i + 1] = sh[threadIdx.x];
    if (threadIdx.x == 255) g_bsum[blockIdx.x] = sh[255];
    if (i == 0) g_off[0] = 0;
}
__global__ __launch_bounds__(256) void scan2_kernel(int nblocks)
{
    __shared__ int sh[256];
    int t = threadIdx.x;
    int v = (t < nblocks) ? g_bsum[t] : 0;
    sh[t] = v;
    __syncthreads();
#pragma unroll
    for (int off = 1; off < 256; off <<= 1) {
        int u = 0;
        if (t >= off) u = sh[t - off];
        __syncthreads();
        if (t >= off) sh[t] += u;
        __syncthreads();
    }
    if (t < nblocks) g_bsum[t] = sh[t] - v;    // exclusive
}
__global__ __launch_bounds__(256) void scan3_kernel()
{
    int i = blockIdx.x * 256 + threadIdx.x;
    if (i < N_NODES) {
        int v = g_off[i + 1] + g_bsum[blockIdx.x];
        g_off[i + 1] = v;
        if (i + 1 < N_NODES) g_fill[i + 1] = v;   // fill cursor = final offset
        if (i == 0) g_fill[0] = 0;
    }
}
__global__ __launch_bounds__(256) void scatter_kernel(const int* __restrict__ ei)
{
    int e = blockIdx.x * blockDim.x + threadIdx.x;
    if (e >= N_EDGES) return;
    int s = ei[e], d = ei[N_EDGES + e];
    int pos = atomicAdd(&g_fill[d], 1);
    g_csrc[pos] = s;
}

// -------- gather attention: one warp per node, fused softmax+agg+relu ------
// Round-4 structure + software pipelining: src index and alpha_src operand
// are prefetched one iteration ahead to break the serial LDG chain.
__global__ __launch_bounds__(256) void gat_gather_kernel(const float* __restrict__ b)
{
    const int warp = threadIdx.x >> 5, lane = threadIdx.x & 31;
    const int n = blockIdx.x * 8 + warp;
    if (n >= N_NODES) return;
    const unsigned FULL = 0xffffffffu;
    const int h0 = lane >> 3, h1 = 4 + (lane >> 3);

    float myasrc = 0.f, myadst = 0.f;
    if (lane < 8) {
        myasrc = g_asrc[n * 8 + lane];
        myadst = g_adst[n * 8 + lane];
    }
    float4 acc0 = make_float4(0.f, 0.f, 0.f, 0.f);
    float4 acc1 = make_float4(0.f, 0.f, 0.f, 0.f);
    float denom = 0.f;

    const int beg = g_off[n], end = g_off[n + 1];

    int s_nxt = 0; float av_nxt = 0.f;
    if (beg < end) {
        s_nxt = g_csrc[beg];
        if (lane < 8) av_nxt = g_asrc[s_nxt * 8 + lane];
    }
    for (int i = beg; i < end; ++i) {
        const int s = s_nxt;
        const float av = av_nxt;
        if (i + 1 < end) {
            s_nxt = g_csrc[i + 1];
            if (lane < 8) av_nxt = g_asrc[s_nxt * 8 + lane];
        }
        float w = 0.f;
        if (lane < 8) {
            w = expf(leaky(av + myadst));
            denom += w;
        }
        float al0 = __shfl_sync(FULL, w, h0);
        float al1 = __shfl_sync(FULL, w, h1);
        float4 v0 = *(const float4*)&g_h[(size_t)s * 256 + lane * 4];
        float4 v1 = *(const float4*)&g_h[(size_t)s * 256 + 128 + lane * 4];
        acc0.x += al0 * v0.x; acc0.y += al0 * v0.y;
        acc0.z += al0 * v0.z; acc0.w += al0 * v0.w;
        acc1.x += al1 * v1.x; acc1.y += al1 * v1.y;
        acc1.z += al1 * v1.z; acc1.w += al1 * v1.w;
    }
    // self loop
    {
        float w = 0.f;
        if (lane < 8) {
            w = expf(leaky(myasrc + myadst));
            denom += w;
        }
        float al0 = __shfl_sync(FULL, w, h0);
        float al1 = __shfl_sync(FULL, w, h1);
        float4 v0 = *(const float4*)&g_h[(size_t)n * 256 + lane * 4];
        float4 v1 = *(const float4*)&g_h[(size_t)n * 256 + 128 + lane * 4];
        acc0.x += al0 * v0.x; acc0.y += al0 * v0.y;
        acc0.z += al0 * v0.z; acc0.w += al0 * v0.w;
        acc1.x += al1 * v1.x; acc1.y += al1 * v1.y;
        acc1.z += al1 * v1.z; acc1.w += al1 * v1.w;
    }
    float inv0 = 1.f / __shfl_sync(FULL, denom, h0);
    float inv1 = 1.f / __shfl_sync(FULL, denom, h1);
    float4 bb0 = *(const float4*)&b[lane * 4];
    float4 bb1 = *(const float4*)&b[128 + lane * 4];
    float4 o0, o1;
    o0.x = fmaxf(acc0.x * inv0 + bb0.x, 0.f);
    o0.y = fmaxf(acc0.y * inv0 + bb0.y, 0.f);
    o0.z = fmaxf(acc0.z * inv0 + bb0.z, 0.f);
    o0.w = fmaxf(acc0.w * inv0 + bb0.w, 0.f);
    o1.x = fmaxf(acc1.x * inv1 + bb1.x, 0.f);
    o1.y = fmaxf(acc1.y * inv1 + bb1.y, 0.f);
    o1.z = fmaxf(acc1.z * inv1 + bb1.z, 0.f);
    o1.w = fmaxf(acc1.w * inv1 + bb1.w, 0.f);
    *(float4*)&g_x[(size_t)n * 256 + lane * 4] = o0;
    *(float4*)&g_x[(size_t)n * 256 + 128 + lane * 4] = o1;
}

// ---------------- pack Wcat = [Wp1_a | Wp1_b] : [256 x 64] ----------------
__global__ __launch_bounds__(256) void pack_wcat_kernel(const float* __restrict__ Wp1)
{
    int i = blockIdx.x * blockDim.x + threadIdx.x;
    if (i >= 256 * 64) return;
    int k = i >> 6, j = i & 63;
    g_wcat[i] = (j < 32) ? Wp1[k * 32 + j] : Wp1[(256 + k) * 32 + (j - 32)];
}

// ---------------- edge predictor: emb MLP + combine (fp32, round-4) --------
__global__ __launch_bounds__(128) void edge_pred_kernel(
    const int* __restrict__ ei, const float* __restrict__ edge_attr,
    const float* __restrict__ Wm1, const float* __restrict__ bm1,
    const float* __restrict__ Wm2, const float* __restrict__ bm2,
    const float* __restrict__ Wp1, const float* __restrict__ bp1,
    const float* __restrict__ Wp2, const float* __restrict__ bp2,
    float* __restrict__ out)
{
    __shared__ float sEA[64 * 33];
    __shared__ float sT1[64 * 33];
    __shared__ float sW[3072];          // Wm1 | Wm2 | Wp1_c
    __shared__ int   sRow[64], sCol[64];
    __shared__ float sB[64];            // bm1 | bm2

    const int tid = threadIdx.x;
    const int tx = tid & 7;
    const int ey = tid >> 3;
    const int e0 = blockIdx.x * 64;

    if (tid < 64) {
        sRow[tid] = ei[e0 + tid];
        sCol[tid] = ei[N_EDGES + e0 + tid];
    }
    for (int i = tid; i < 3072; i += 128)
        sW[i] = (i < 1024) ? Wm1[i]
              : (i < 2048) ? Wm2[i - 1024]
                           : Wp1[512 * 32 + (i - 2048)];
    if (tid < 32) { sB[tid] = bm1[tid]; sB[32 + tid] = bm2[tid]; }
    for (int f = tid; f < 64 * 8; f += 128) {
        int e = f >> 3, q = f & 7;
        float4 v = *(const float4*)&edge_attr[(size_t)(e0 + e) * 32 + q * 4];
        float* p = &sEA[e * 33 + q * 4];
        p[0] = v.x; p[1] = v.y; p[2] = v.z; p[3] = v.w;
    }
    __syncthreads();

    // layer 1: T1 = relu(EA @ Wm1 + bm1)
    {
        float acc[4][4];
#pragma unroll
        for (int i = 0; i < 4; ++i)
#pragma unroll
            for (int j = 0; j < 4; ++j) acc[i][j] = 0.f;
#pragma unroll
        for (int k = 0; k < 32; ++k) {
            float4 w = *(const float4*)&sW[k * 32 + tx * 4];
#pragma unroll
            for (int i = 0; i < 4; ++i) {
                float a = sEA[(ey * 4 + i) * 33 + k];
                acc[i][0] += a * w.x; acc[i][1] += a * w.y;
                acc[i][2] += a * w.z; acc[i][3] += a * w.w;
            }
        }
#pragma unroll
        for (int i = 0; i < 4; ++i)
#pragma unroll
            for (int j = 0; j < 4; ++j) {
                float v = acc[i][j] + sB[tx * 4 + j];
                sT1[(ey * 4 + i) * 33 + tx * 4 + j] = v > 0.f ? v : 0.f;
            }
    }
    __syncthreads();
    // layer 2: EMB = relu(T1 @ Wm2 + bm2) -> sEA (reuse)
    {
        float acc[4][4];
#pragma unroll
        for (int i = 0; i < 4; ++i)
#pragma unroll
            for (int j = 0; j < 4; ++j) acc[i][j] = 0.f;
#pragma unroll
        for (int k = 0; k < 32; ++k) {
            float4 w = *(const float4*)&sW[1024 + k * 32 + tx * 4];
#pragma unroll
            for (int i = 0; i < 4; ++i) {
                float a = sT1[(ey * 4 + i) * 33 + k];
                acc[i][0] += a * w.x; acc[i][1] += a * w.y;
                acc[i][2] += a * w.z; acc[i][3] += a * w.w;
            }
        }
        __syncthreads();
#pragma unroll
        for (int i = 0; i < 4; ++i)
#pragma unroll
            for (int j = 0; j < 4; ++j) {
                float v = acc[i][j] + sB[32 + tx * 4 + j];
                sEA[(ey * 4 + i) * 33 + tx * 4 + j] = v > 0.f ? v : 0.f;
            }
    }
    __syncthreads();
    // layer 3: acc = EMB @ Wp1_c
    float acc[4][4];
#pragma unroll
    for (int i = 0; i < 4; ++i)
#pragma unroll
        for (int j = 0; j < 4; ++j) acc[i][j] = 0.f;
#pragma unroll
    for (int k = 0; k < 32; ++k) {
        float4 w = *(const float4*)&sW[2048 + k * 32 + tx * 4];
#pragma unroll
        for (int i = 0; i < 4; ++i) {
            float a = sEA[(ey * 4 + i) * 33 + k];
            acc[i][0] += a * w.x; acc[i][1] += a * w.y;
            acc[i][2] += a * w.z; acc[i][3] += a * w.w;
        }
    }

    // epilogue: pre = acc + P_a[row] + P_b[col] + bp1; out = relu(pre)@Wp2 + bp2
    float4 bp = *(const float4*)&bp1[tx * 4];
    float4 wp = *(const float4*)&Wp2[tx * 4];
    float bias2 = bp2[0];
#pragma unroll
    for (int i = 0; i < 4; ++i) {
        int e = ey * 4 + i;
        int r = sRow[e], c = sCol[e];
        float4 pa = *(const float4*)&g_p[(size_t)r * 64 + tx * 4];
        float4 pb = *(const float4*)&g_p[(size_t)c * 64 + 32 + tx * 4];
        float h0 = acc[i][0] + pa.x + pb.x + bp.x; h0 = h0 > 0.f ? h0 : 0.f;
        float h1 = acc[i][1] + pa.y + pb.y + bp.y; h1 = h1 > 0.f ? h1 : 0.f;
        float h2 = acc[i][2] + pa.z + pb.z + bp.z; h2 = h2 > 0.f ? h2 : 0.f;
        float h3 = acc[i][3] + pa.w + pb.w + bp.w; h3 = h3 > 0.f ? h3 : 0.f;
        float p = h0 * wp.x + h1 * wp.y + h2 * wp.z + h3 * wp.w;
        p += __shfl_down_sync(0xffffffffu, p, 4, 8);
        p += __shfl_down_sync(0xffffffffu, p, 2, 8);
        p += __shfl_down_sync(0xffffffffu, p, 1, 8);
        if (tx == 0) out[e0 + e] = p + bias2;
    }
}

// ---------------- host ----------------
extern "C" void kernel_launch(void* const* d_in, const int* in_sizes, int n_in,
                              void* d_out, int out_size)
{
    const float* x   = (const float*)d_in[0];
    const int*   ei  = (const int*)d_in[1];
    const float* ea  = (const float*)d_in[2];
    const float* W1  = (const float*)d_in[3];
    const float* as1 = (const float*)d_in[4];
    const float* ad1 = (const float*)d_in[5];
    const float* b1  = (const float*)d_in[6];
    const float* W2  = (const float*)d_in[7];
    const float* as2 = (const float*)d_in[8];
    const float* ad2 = (const float*)d_in[9];
    const float* b2  = (const float*)d_in[10];
    const float* Wm1 = (const float*)d_in[11];
    const float* bm1 = (const float*)d_in[12];
    const float* Wm2 = (const float*)d_in[13];
    const float* bm2 = (const float*)d_in[14];
    const float* Wp1 = (const float*)d_in[15];
    const float* bp1 = (const float*)d_in[16];
    const float* Wp2 = (const float*)d_in[17];
    const float* bp2 = (const float*)d_in[18];
    float* out = (float*)d_out;

    float *ph = nullptr, *px = nullptr, *pw = nullptr, *pp = nullptr;
    cudaGetSymbolAddress((void**)&ph, g_h);
    cudaGetSymbolAddress((void**)&px, g_x);
    cudaGetSymbolAddress((void**)&pw, g_wcat);
    cudaGetSymbolAddress((void**)&pp, g_p);

    const int EB  = (N_EDGES + 255) / 256;
    const int NB  = (N_NODES + 255) / 256;
    const int NWB = (N_NODES + 7) / 8;

    // ---- CSR build (once; reused by both layers) ----
    zero_cnt_kernel<<<NB, 256>>>();
    count_kernel<<<EB, 256>>>(ei);
    scan1_kernel<<<NB, 256>>>();
    scan2_kernel<<<1, 256>>>(NB);
    scan3_kernel<<<NB, 256>>>();
    scatter_kernel<<<EB, 256>>>(ei);

    for (int layer = 0; layer < 2; ++layer) {
        const float* X   = layer ? px : x;
        const int    K   = layer ? 256 : 128;
        const float* W   = layer ? W2 : W1;
        const float* as_ = layer ? as2 : as1;
        const float* ad_ = layer ? ad2 : ad1;
        const float* b_  = layer ? b2 : b1;

        sgemm_kernel<<<dim3(391, 4), 256>>>(X, W, ph, N_NODES, K, 256, 256, as_, ad_);
        gat_gather_kernel<<<NWB, 256>>>(b_);
    }
    pack_wcat_kernel<<<64, 256>>>(Wp1);
    sgemm_kernel<<<dim3(391, 1), 256>>>(px, pw, pp, N_NODES, 256, 64, 64,
                                        nullptr, nullptr);
    edge_pred_kernel<<<N_EDGES / 64, 128>>>(ei, ea,
                                            Wm1, bm1, Wm2, bm2,
                                            Wp1, bp1, Wp2, bp2, out);
}

// round 8
// speedup vs baseline: 1.4921x; 1.0134x over previous
#include <cuda_runtime.h>
#include <math.h>

#define N_NODES 50000
#define N_EDGES 400000
#define HEADS 8
#define HID 32
#define F 256            // HEADS*HID
#define NEG 0.2f

// ---------------- scratch (device globals: allocation-free) ----------------
__device__ float g_h[N_NODES * F];        // X @ W (pre-attention features)
__device__ float g_x[N_NODES * F];        // layer output
__device__ float g_asrc[N_NODES * HEADS];
__device__ float g_adst[N_NODES * HEADS];
__device__ float g_p[N_NODES * 64];       // [P_a | P_b] node projections
__device__ float g_wcat[256 * 64];        // [Wp1_a | Wp1_b] packed
__device__ int   g_cnt[N_NODES];
__device__ int   g_off[N_NODES + 1];
__device__ int   g_fill[N_NODES];
__device__ int   g_bsum[256];
__device__ int   g_csrc[N_EDGES];

__device__ __forceinline__ float leaky(float x) { return x > 0.f ? x : NEG * x; }

// ---------------- SGEMM: C[M x N] = A[M x K] @ B[K x N] -------------------
// 128x64 tile, BK=16, 256 threads, 8x4 micro-tile.
// Register-prefetch double buffering: next tile's LDGs are issued before the
// current tile's compute, hiding global latency under the FFMA phase.
// Optional fused epilogue: per-row attention dots for the 2 heads in this tile.
__global__ __launch_bounds__(256) void sgemm_kernel(
    const float* __restrict__ A, const float* __restrict__ B,
    float* __restrict__ C, int M, int K, int ldb, int ldc,
    const float* __restrict__ a_src, const float* __restrict__ a_dst)
{
    __shared__ float As[16][128];
    __shared__ float Bs[16][64];
    __shared__ float sAs[64], sAd[64];
    const int tid = threadIdx.x;
    const int tx = tid & 15;
    const int ty = tid >> 4;
    const int m0 = blockIdx.x * 128;
    const int n0 = blockIdx.y * 64;

    if (a_src != nullptr && tid < 64) {
        sAs[tid] = a_src[n0 + tid];
        sAd[tid] = a_dst[n0 + tid];
    }

    // A-load coords (2 fragments per thread), B-load coords (1 per thread)
    const int am0 = tid >> 2;                  // fragment 0 row
    const int am1 = (tid + 256) >> 2;          // fragment 1 row
    const int akq = (tid & 3) * 4;             // k quad within tile
    const int bkk = tid >> 4;
    const int bnq = (tid & 15) * 4;

    float acc[8][4];
#pragma unroll
    for (int i = 0; i < 8; ++i)
#pragma unroll
        for (int j = 0; j < 4; ++j) acc[i][j] = 0.f;

    // prologue: load tile 0 into registers
    float4 pa0 = make_float4(0.f, 0.f, 0.f, 0.f);
    float4 pa1 = make_float4(0.f, 0.f, 0.f, 0.f);
    float4 pb;
    if (m0 + am0 < M) pa0 = *(const float4*)&A[(size_t)(m0 + am0) * K + akq];
    if (m0 + am1 < M) pa1 = *(const float4*)&A[(size_t)(m0 + am1) * K + akq];
    pb = *(const float4*)&B[(size_t)bkk * ldb + n0 + bnq];

    for (int k0 = 0; k0 < K; k0 += 16) {
        // store current tile to smem
        As[akq + 0][am0] = pa0.x; As[akq + 1][am0] = pa0.y;
        As[akq + 2][am0] = pa0.z; As[akq + 3][am0] = pa0.w;
        As[akq + 0][am1] = pa1.x; As[akq + 1][am1] = pa1.y;
        As[akq + 2][am1] = pa1.z; As[akq + 3][am1] = pa1.w;
        *(float4*)&Bs[bkk][bnq] = pb;
        __syncthreads();

        // prefetch next tile into registers (latency overlapped with compute)
        if (k0 + 16 < K) {
            pa0 = make_float4(0.f, 0.f, 0.f, 0.f);
            pa1 = make_float4(0.f, 0.f, 0.f, 0.f);
            if (m0 + am0 < M) pa0 = *(const float4*)&A[(size_t)(m0 + am0) * K + k0 + 16 + akq];
            if (m0 + am1 < M) pa1 = *(const float4*)&A[(size_t)(m0 + am1) * K + k0 + 16 + akq];
            pb = *(const float4*)&B[(size_t)(k0 + 16 + bkk) * ldb + n0 + bnq];
        }

#pragma unroll
        for (int kk = 0; kk < 16; ++kk) {
            float4 b4 = *(float4*)&Bs[kk][tx * 4];
            float4 a0 = *(float4*)&As[kk][ty * 8];
            float4 a1 = *(float4*)&As[kk][ty * 8 + 4];
            float a[8] = {a0.x, a0.y, a0.z, a0.w, a1.x, a1.y, a1.z, a1.w};
#pragma unroll
            for (int i = 0; i < 8; ++i) {
                acc[i][0] += a[i] * b4.x; acc[i][1] += a[i] * b4.y;
                acc[i][2] += a[i] * b4.z; acc[i][3] += a[i] * b4.w;
            }
        }
        __syncthreads();
    }
#pragma unroll
    for (int i = 0; i < 8; ++i) {
        int m = m0 + ty * 8 + i;
        if (m < M)
            *(float4*)&C[(size_t)m * ldc + n0 + tx * 4] =
                make_float4(acc[i][0], acc[i][1], acc[i][2], acc[i][3]);
    }
    if (a_src != nullptr) {
        float4 wa = *(float4*)&sAs[tx * 4];
        float4 wd = *(float4*)&sAd[tx * 4];
#pragma unroll
        for (int i = 0; i < 8; ++i) {
            float ps = acc[i][0] * wa.x + acc[i][1] * wa.y + acc[i][2] * wa.z + acc[i][3] * wa.w;
            float pd = acc[i][0] * wd.x + acc[i][1] * wd.y + acc[i][2] * wd.z + acc[i][3] * wd.w;
            ps += __shfl_down_sync(0xffffffffu, ps, 4, 8);
            ps += __shfl_down_sync(0xffffffffu, ps, 2, 8);
            ps += __shfl_down_sync(0xffffffffu, ps, 1, 8);
            pd += __shfl_down_sync(0xffffffffu, pd, 4, 8);
            pd += __shfl_down_sync(0xffffffffu, pd, 2, 8);
            pd += __shfl_down_sync(0xffffffffu, pd, 1, 8);
            int m = m0 + ty * 8 + i;
            if ((tx & 7) == 0 && m < M) {
                int head = (n0 >> 5) + (tx >> 3);
                g_asrc[m * 8 + head] = ps;
                g_adst[m * 8 + head] = pd;
            }
        }
    }
}

// ---------------- CSR build ----------------
__global__ __launch_bounds__(256) void zero_cnt_kernel()
{
    int i = blockIdx.x * blockDim.x + threadIdx.x;
    if (i < N_NODES) g_cnt[i] = 0;
}
__global__ __launch_bounds__(256) void count_kernel(const int* __restrict__ ei)
{
    int e = blockIdx.x * blockDim.x + threadIdx.x;
    if (e < N_EDGES) atomicAdd(&g_cnt[ei[N_EDGES + e]], 1);
}
__global__ __launch_bounds__(256) void scan1_kernel()
{
    __shared__ int sh[256];
    int i = blockIdx.x * 256 + threadIdx.x;
    int v = (i < N_NODES) ? g_cnt[i] : 0;
    sh[threadIdx.x] = v;
    __syncthreads();
#pragma unroll
    for (int off = 1; off < 256; off <<= 1) {
        int t = 0;
        if (threadIdx.x >= off) t = sh[threadIdx.x - off];
        __syncthreads();
        if (threadIdx.x >= off) sh[threadIdx.x] += t;
        __syncthreads();
    }
    if (i < N_NODES) g_off[i + 1] = sh[threadIdx.x];
    if (threadIdx.x == 255) g_bsum[blockIdx.x] = sh[255];
    if (i == 0) g_off[0] = 0;
}
__global__ __launch_bounds__(256) void scan2_kernel(int nblocks)
{
    __shared__ int sh[256];
    int t = threadIdx.x;
    int v = (t < nblocks) ? g_bsum[t] : 0;
    sh[t] = v;
    __syncthreads();
#pragma unroll
    for (int off = 1; off < 256; off <<= 1) {
        int u = 0;
        if (t >= off) u = sh[t - off];
        __syncthreads();
        if (t >= off) sh[t] += u;
        __syncthreads();
    }
    if (t < nblocks) g_bsum[t] = sh[t] - v;    // exclusive
}
__global__ __launch_bounds__(256) void scan3_kernel()
{
    int i = blockIdx.x * 256 + threadIdx.x;
    if (i < N_NODES) {
        int v = g_off[i + 1] + g_bsum[blockIdx.x];
        g_off[i + 1] = v;
        if (i + 1 < N_NODES) g_fill[i + 1] = v;   // fill cursor = final offset
        if (i == 0) g_fill[0] = 0;
    }
}
__global__ __launch_bounds__(256) void scatter_kernel(const int* __restrict__ ei)
{
    int e = blockIdx.x * blockDim.x + threadIdx.x;
    if (e >= N_EDGES) return;
    int s = ei[e], d = ei[N_EDGES + e];
    int pos = atomicAdd(&g_fill[d], 1);
    g_csrc[pos] = s;
}

// -------- gather attention: one warp per node, fused softmax+agg+relu ------
// (round-4 body: simple loop; warp parallelism hides latency)
__global__ __launch_bounds__(256) void gat_gather_kernel(const float* __restrict__ b)
{
    const int warp = threadIdx.x >> 5, lane = threadIdx.x & 31;
    const int n = blockIdx.x * 8 + warp;
    if (n >= N_NODES) return;
    const unsigned FULL = 0xffffffffu;
    const int h0 = lane >> 3, h1 = 4 + (lane >> 3);

    float myasrc = 0.f, myadst = 0.f;
    if (lane < 8) {
        myasrc = g_asrc[n * 8 + lane];
        myadst = g_adst[n * 8 + lane];
    }
    float4 acc0 = make_float4(0.f, 0.f, 0.f, 0.f);
    float4 acc1 = make_float4(0.f, 0.f, 0.f, 0.f);
    float denom = 0.f;

    const int beg = g_off[n], end = g_off[n + 1];
    for (int i = beg; i < end; ++i) {
        int s = g_csrc[i];
        float w = 0.f;
        if (lane < 8) {
            w = expf(leaky(g_asrc[s * 8 + lane] + myadst));
            denom += w;
        }
        float al0 = __shfl_sync(FULL, w, h0);
        float al1 = __shfl_sync(FULL, w, h1);
        float4 v0 = *(const float4*)&g_h[(size_t)s * 256 + lane * 4];
        float4 v1 = *(const float4*)&g_h[(size_t)s * 256 + 128 + lane * 4];
        acc0.x += al0 * v0.x; acc0.y += al0 * v0.y;
        acc0.z += al0 * v0.z; acc0.w += al0 * v0.w;
        acc1.x += al1 * v1.x; acc1.y += al1 * v1.y;
        acc1.z += al1 * v1.z; acc1.w += al1 * v1.w;
    }
    // self loop
    {
        float w = 0.f;
        if (lane < 8) {
            w = expf(leaky(myasrc + myadst));
            denom += w;
        }
        float al0 = __shfl_sync(FULL, w, h0);
        float al1 = __shfl_sync(FULL, w, h1);
        float4 v0 = *(const float4*)&g_h[(size_t)n * 256 + lane * 4];
        float4 v1 = *(const float4*)&g_h[(size_t)n * 256 + 128 + lane * 4];
        acc0.x += al0 * v0.x; acc0.y += al0 * v0.y;
        acc0.z += al0 * v0.z; acc0.w += al0 * v0.w;
        acc1.x += al1 * v1.x; acc1.y += al1 * v1.y;
        acc1.z += al1 * v1.z; acc1.w += al1 * v1.w;
    }
    float inv0 = 1.f / __shfl_sync(FULL, denom, h0);
    float inv1 = 1.f / __shfl_sync(FULL, denom, h1);
    float4 bb0 = *(const float4*)&b[lane * 4];
    float4 bb1 = *(const float4*)&b[128 + lane * 4];
    float4 o0, o1;
    o0.x = fmaxf(acc0.x * inv0 + bb0.x, 0.f);
    o0.y = fmaxf(acc0.y * inv0 + bb0.y, 0.f);
    o0.z = fmaxf(acc0.z * inv0 + bb0.z, 0.f);
    o0.w = fmaxf(acc0.w * inv0 + bb0.w, 0.f);
    o1.x = fmaxf(acc1.x * inv1 + bb1.x, 0.f);
    o1.y = fmaxf(acc1.y * inv1 + bb1.y, 0.f);
    o1.z = fmaxf(acc1.z * inv1 + bb1.z, 0.f);
    o1.w = fmaxf(acc1.w * inv1 + bb1.w, 0.f);
    *(float4*)&g_x[(size_t)n * 256 + lane * 4] = o0;
    *(float4*)&g_x[(size_t)n * 256 + 128 + lane * 4] = o1;
}

// ---------------- pack Wcat = [Wp1_a | Wp1_b] : [256 x 64] ----------------
__global__ __launch_bounds__(256) void pack_wcat_kernel(const float* __restrict__ Wp1)
{
    int i = blockIdx.x * blockDim.x + threadIdx.x;
    if (i >= 256 * 64) return;
    int k = i >> 6, j = i & 63;
    g_wcat[i] = (j < 32) ? Wp1[k * 32 + j] : Wp1[(256 + k) * 32 + (j - 32)];
}

// ---------------- edge predictor: emb MLP + combine (fp32, round-4) --------
__global__ __launch_bounds__(128) void edge_pred_kernel(
    const int* __restrict__ ei, const float* __restrict__ edge_attr,
    const float* __restrict__ Wm1, const float* __restrict__ bm1,
    const float* __restrict__ Wm2, const float* __restrict__ bm2,
    const float* __restrict__ Wp1, const float* __restrict__ bp1,
    const float* __restrict__ Wp2, const float* __restrict__ bp2,
    float* __restrict__ out)
{
    __shared__ float sEA[64 * 33];
    __shared__ float sT1[64 * 33];
    __shared__ float sW[3072];          // Wm1 | Wm2 | Wp1_c
    __shared__ int   sRow[64], sCol[64];
    __shared__ float sB[64];            // bm1 | bm2

    const int tid = threadIdx.x;
    const int tx = tid & 7;
    const int ey = tid >> 3;
    const int e0 = blockIdx.x * 64;

    if (tid < 64) {
        sRow[tid] = ei[e0 + tid];
        sCol[tid] = ei[N_EDGES + e0 + tid];
    }
    for (int i = tid; i < 3072; i += 128)
        sW[i] = (i < 1024) ? Wm1[i]
              : (i < 2048) ? Wm2[i - 1024]
                           : Wp1[512 * 32 + (i - 2048)];
    if (tid < 32) { sB[tid] = bm1[tid]; sB[32 + tid] = bm2[tid]; }
    for (int f = tid; f < 64 * 8; f += 128) {
        int e = f >> 3, q = f & 7;
        float4 v = *(const float4*)&edge_attr[(size_t)(e0 + e) * 32 + q * 4];
        float* p = &sEA[e * 33 + q * 4];
        p[0] = v.x; p[1] = v.y; p[2] = v.z; p[3] = v.w;
    }
    __syncthreads();

    // layer 1: T1 = relu(EA @ Wm1 + bm1)
    {
        float acc[4][4];
#pragma unroll
        for (int i = 0; i < 4; ++i)
#pragma unroll
            for (int j = 0; j < 4; ++j) acc[i][j] = 0.f;
#pragma unroll
        for (int k = 0; k < 32; ++k) {
            float4 w = *(const float4*)&sW[k * 32 + tx * 4];
#pragma unroll
            for (int i = 0; i < 4; ++i) {
                float a = sEA[(ey * 4 + i) * 33 + k];
                acc[i][0] += a * w.x; acc[i][1] += a * w.y;
                acc[i][2] += a * w.z; acc[i][3] += a * w.w;
            }
        }
#pragma unroll
        for (int i = 0; i < 4; ++i)
#pragma unroll
            for (int j = 0; j < 4; ++j) {
                float v = acc[i][j] + sB[tx * 4 + j];
                sT1[(ey * 4 + i) * 33 + tx * 4 + j] = v > 0.f ? v : 0.f;
            }
    }
    __syncthreads();
    // layer 2: EMB = relu(T1 @ Wm2 + bm2) -> sEA (reuse)
    {
        float acc[4][4];
#pragma unroll
        for (int i = 0; i < 4; ++i)
#pragma unroll
            for (int j = 0; j < 4; ++j) acc[i][j] = 0.f;
#pragma unroll
        for (int k = 0; k < 32; ++k) {
            float4 w = *(const float4*)&sW[1024 + k * 32 + tx * 4];
#pragma unroll
            for (int i = 0; i < 4; ++i) {
                float a = sT1[(ey * 4 + i) * 33 + k];
                acc[i][0] += a * w.x; acc[i][1] += a * w.y;
                acc[i][2] += a * w.z; acc[i][3] += a * w.w;
            }
        }
        __syncthreads();
#pragma unroll
        for (int i = 0; i < 4; ++i)
#pragma unroll
            for (int j = 0; j < 4; ++j) {
                float v = acc[i][j] + sB[32 + tx * 4 + j];
                sEA[(ey * 4 + i) * 33 + tx * 4 + j] = v > 0.f ? v : 0.f;
            }
    }
    __syncthreads();
    // layer 3: acc = EMB @ Wp1_c
    float acc[4][4];
#pragma unroll
    for (int i = 0; i < 4; ++i)
#pragma unroll
        for (int j = 0; j < 4; ++j) acc[i][j] = 0.f;
#pragma unroll
    for (int k = 0; k < 32; ++k) {
        float4 w = *(const float4*)&sW[2048 + k * 32 + tx * 4];
#pragma unroll
        for (int i = 0; i < 4; ++i) {
            float a = sEA[(ey * 4 + i) * 33 + k];
            acc[i][0] += a * w.x; acc[i][1] += a * w.y;
            acc[i][2] += a * w.z; acc[i][3] += a * w.w;
        }
    }

    // epilogue: pre = acc + P_a[row] + P_b[col] + bp1; out = relu(pre)@Wp2 + bp2
    float4 bp = *(const float4*)&bp1[tx * 4];
    float4 wp = *(const float4*)&Wp2[tx * 4];
    float bias2 = bp2[0];
#pragma unroll
    for (int i = 0; i < 4; ++i) {
        int e = ey * 4 + i;
        int r = sRow[e], c = sCol[e];
        float4 pa = *(const float4*)&g_p[(size_t)r * 64 + tx * 4];
        float4 pb = *(const float4*)&g_p[(size_t)c * 64 + 32 + tx * 4];
        float h0 = acc[i][0] + pa.x + pb.x + bp.x; h0 = h0 > 0.f ? h0 : 0.f;
        float h1 = acc[i][1] + pa.y + pb.y + bp.y; h1 = h1 > 0.f ? h1 : 0.f;
        float h2 = acc[i][2] + pa.z + pb.z + bp.z; h2 = h2 > 0.f ? h2 : 0.f;
        float h3 = acc[i][3] + pa.w + pb.w + bp.w; h3 = h3 > 0.f ? h3 : 0.f;
        float p = h0 * wp.x + h1 * wp.y + h2 * wp.z + h3 * wp.w;
        p += __shfl_down_sync(0xffffffffu, p, 4, 8);
        p += __shfl_down_sync(0xffffffffu, p, 2, 8);
        p += __shfl_down_sync(0xffffffffu, p, 1, 8);
        if (tx == 0) out[e0 + e] = p + bias2;
    }
}

// ---------------- host ----------------
extern "C" void kernel_launch(void* const* d_in, const int* in_sizes, int n_in,
                              void* d_out, int out_size)
{
    const float* x   = (const float*)d_in[0];
    const int*   ei  = (const int*)d_in[1];
    const float* ea  = (const float*)d_in[2];
    const float* W1  = (const float*)d_in[3];
    const float* as1 = (const float*)d_in[4];
    const float* ad1 = (const float*)d_in[5];
    const float* b1  = (const float*)d_in[6];
    const float* W2  = (const float*)d_in[7];
    const float* as2 = (const float*)d_in[8];
    const float* ad2 = (const float*)d_in[9];
    const float* b2  = (const float*)d_in[10];
    const float* Wm1 = (const float*)d_in[11];
    const float* bm1 = (const float*)d_in[12];
    const float* Wm2 = (const float*)d_in[13];
    const float* bm2 = (const float*)d_in[14];
    const float* Wp1 = (const float*)d_in[15];
    const float* bp1 = (const float*)d_in[16];
    const float* Wp2 = (const float*)d_in[17];
    const float* bp2 = (const float*)d_in[18];
    float* out = (float*)d_out;

    float *ph = nullptr, *px = nullptr, *pw = nullptr, *pp = nullptr;
    cudaGetSymbolAddress((void**)&ph, g_h);
    cudaGetSymbolAddress((void**)&px, g_x);
    cudaGetSymbolAddress((void**)&pw, g_wcat);
    cudaGetSymbolAddress((void**)&pp, g_p);

    const int EB  = (N_EDGES + 255) / 256;
    const int NB  = (N_NODES + 255) / 256;
    const int NWB = (N_NODES + 7) / 8;

    // ---- CSR build (once; reused by both layers) ----
    zero_cnt_kernel<<<NB, 256>>>();
    count_kernel<<<EB, 256>>>(ei);
    scan1_kernel<<<NB, 256>>>();
    scan2_kernel<<<1, 256>>>(NB);
    scan3_kernel<<<NB, 256>>>();
    scatter_kernel<<<EB, 256>>>(ei);

    for (int layer = 0; layer < 2; ++layer) {
        const float* X   = layer ? px : x;
        const int    K   = layer ? 256 : 128;
        const float* W   = layer ? W2 : W1;
        const float* as_ = layer ? as2 : as1;
        const float* ad_ = layer ? ad2 : ad1;
        const float* b_  = layer ? b2 : b1;

        sgemm_kernel<<<dim3(391, 4), 256>>>(X, W, ph, N_NODES, K, 256, 256, as_, ad_);
        gat_gather_kernel<<<NWB, 256>>>(b_);
    }
    pack_wcat_kernel<<<64, 256>>>(Wp1);
    sgemm_kernel<<<dim3(391, 1), 256>>>(px, pw, pp, N_NODES, 256, 64, 64,
                                        nullptr, nullptr);
    edge_pred_kernel<<<N_EDGES / 64, 128>>>(ei, ea,
                                            Wm1, bm1, Wm2, bm2,
                                            Wp1, bp1, Wp2, bp2, out);
}

// round 9
// speedup vs baseline: 1.9158x; 1.2839x over previous
#include <cuda_runtime.h>
#include <cuda_bf16.h>
#include <math.h>

#define N_NODES 50000
#define N_EDGES 400000
#define HEADS 8
#define HID 32
#define F 256            // HEADS*HID
#define NEG 0.2f

// ---------------- scratch (device globals: allocation-free) ----------------
__device__ float g_h[N_NODES * F];        // X @ W (pre-attention features)
__device__ float g_x[N_NODES * F];        // layer output
__device__ float g_asrc[N_NODES * HEADS];
__device__ float g_adst[N_NODES * HEADS];
__device__ float g_p[N_NODES * 64];       // [P_a | P_b] node projections
__device__ float g_wcat[256 * 64];        // [Wp1_a | Wp1_b] packed
__device__ int   g_cnt[N_NODES];
__device__ int   g_off[N_NODES + 1];
__device__ int   g_fill[N_NODES];
__device__ int   g_bsum[256];
__device__ int   g_csrc[N_EDGES];

__device__ __forceinline__ float leaky(float x) { return x > 0.f ? x : NEG * x; }

// pack two floats to bf16x2 (x in low half = first k element)
__device__ __forceinline__ unsigned pk(float x, float y) {
    __nv_bfloat162 h = __floats2bfloat162_rn(x, y);
    return *(unsigned*)&h;
}
__device__ __forceinline__ void split2(float x, float y, unsigned& hi, unsigned& lo) {
    float hx = __bfloat162float(__float2bfloat16_rn(x));
    float hy = __bfloat162float(__float2bfloat16_rn(y));
    hi = pk(hx, hy);
    lo = pk(x - hx, y - hy);
}

__device__ __forceinline__ void mma16(float* c,
    unsigned a0, unsigned a1, unsigned a2, unsigned a3,
    unsigned b0, unsigned b1)
{
    asm volatile(
        "mma.sync.aligned.m16n8k16.row.col.f32.bf16.bf16.f32 "
        "{%0,%1,%2,%3}, {%4,%5,%6,%7}, {%8,%9}, {%0,%1,%2,%3};"
        : "+f"(c[0]), "+f"(c[1]), "+f"(c[2]), "+f"(c[3])
        : "r"(a0), "r"(a1), "r"(a2), "r"(a3), "r"(b0), "r"(b1));
}

// ------ 3x bf16 split GEMM: C[M x N] = A[M x K] @ B[K x N], tile 128x64 ----
// 256 threads = 8 warps (4 warp_m x 2 warp_n), warp tile 32x32, BK=16.
// a = hi + lo (bf16 each); C = Ah Bh + Al Bh + Ah Bl  (error ~2^-18: < 1e-4)
// Optional fused epilogue: per-row attention dots (2 heads per block tile).
__global__ __launch_bounds__(256) void tc_gemm_kernel(
    const float* __restrict__ A, const float* __restrict__ B,
    float* __restrict__ C, int M, int K, int ldb, int ldc,
    const float* __restrict__ a_src, const float* __restrict__ a_dst)
{
    // [k-pair][m or n] packed bf16x2 along k
    __shared__ unsigned Ah[8][132], Al[8][132];
    __shared__ unsigned Bh[8][68],  Bl[8][68];
    __shared__ float sAs[64], sAd[64];

    const int tid = threadIdx.x;
    const int lane = tid & 31;
    const int wid = tid >> 5;
    const int warp_m = wid >> 1;          // rows warp_m*32
    const int warp_n = wid & 1;           // cols warp_n*32
    const int tig = lane & 3;
    const int grp = lane >> 2;
    const int m0 = blockIdx.x * 128;
    const int n0 = blockIdx.y * 64;

    if (a_src != nullptr && tid < 64) {
        sAs[tid] = a_src[n0 + tid];
        sAd[tid] = a_dst[n0 + tid];
    }

    // A-load coords: two 128-row fragments, 4 consecutive k each
    const int am0 = tid >> 2;             // 0..63
    const int am1 = am0 + 64;             // 64..127
    const int akp = (tid & 3) * 2;        // k-pair base (covers k akp*2..akp*2+3)
    // B-load coords: n = tid&63, k-pair halves
    const int bn = tid & 63;
    const int bkh = tid >> 6;             // 0..3 -> kp {bkh, bkh+4}

    float acc[2][4][4];
#pragma unroll
    for (int mf = 0; mf < 2; ++mf)
#pragma unroll
        for (int nf = 0; nf < 4; ++nf)
#pragma unroll
            for (int j = 0; j < 4; ++j) acc[mf][nf][j] = 0.f;

    for (int k0 = 0; k0 < K; k0 += 16) {
        // ---- A tile: 128x16 -> hi/lo packed pairs ----
        {
            float4 v = make_float4(0.f, 0.f, 0.f, 0.f);
            if (m0 + am0 < M) v = *(const float4*)&A[(size_t)(m0 + am0) * K + k0 + akp * 2];
            unsigned h, l;
            split2(v.x, v.y, h, l); Ah[akp][am0] = h;     Al[akp][am0] = l;
            split2(v.z, v.w, h, l); Ah[akp + 1][am0] = h; Al[akp + 1][am0] = l;
        }
        {
            float4 v = make_float4(0.f, 0.f, 0.f, 0.f);
            if (m0 + am1 < M) v = *(const float4*)&A[(size_t)(m0 + am1) * K + k0 + akp * 2];
            unsigned h, l;
            split2(v.x, v.y, h, l); Ah[akp][am1] = h;     Al[akp][am1] = l;
            split2(v.z, v.w, h, l); Ah[akp + 1][am1] = h; Al[akp + 1][am1] = l;
        }
        // ---- B tile: 16x64 -> hi/lo packed pairs ----
#pragma unroll
        for (int q = 0; q < 2; ++q) {
            int kp = bkh + q * 4;
            float f0 = B[(size_t)(k0 + 2 * kp) * ldb + n0 + bn];
            float f1 = B[(size_t)(k0 + 2 * kp + 1) * ldb + n0 + bn];
            unsigned h, l;
            split2(f0, f1, h, l);
            Bh[kp][bn] = h; Bl[kp][bn] = l;
        }
        __syncthreads();

        // ---- fragments + 24 MMAs ----
        unsigned ah[2][4], al_[2][4];
#pragma unroll
        for (int mf = 0; mf < 2; ++mf) {
            int mb = warp_m * 32 + mf * 16 + grp;
            ah[mf][0] = Ah[tig][mb];      al_[mf][0] = Al[tig][mb];
            ah[mf][1] = Ah[tig][mb + 8];  al_[mf][1] = Al[tig][mb + 8];
            ah[mf][2] = Ah[tig + 4][mb];      al_[mf][2] = Al[tig + 4][mb];
            ah[mf][3] = Ah[tig + 4][mb + 8];  al_[mf][3] = Al[tig + 4][mb + 8];
        }
#pragma unroll
        for (int nf = 0; nf < 4; ++nf) {
            int n = warp_n * 32 + nf * 8 + grp;
            unsigned bh0 = Bh[tig][n], bh1 = Bh[tig + 4][n];
            unsigned bl0 = Bl[tig][n], bl1 = Bl[tig + 4][n];
#pragma unroll
            for (int mf = 0; mf < 2; ++mf) {
                mma16(acc[mf][nf], ah[mf][0], ah[mf][1], ah[mf][2], ah[mf][3], bh0, bh1);
                mma16(acc[mf][nf], al_[mf][0], al_[mf][1], al_[mf][2], al_[mf][3], bh0, bh1);
                mma16(acc[mf][nf], ah[mf][0], ah[mf][1], ah[mf][2], ah[mf][3], bl0, bl1);
            }
        }
        __syncthreads();
    }

    // ---- store C (same fragment mapping as round-5, verified) ----
#pragma unroll
    for (int mf = 0; mf < 2; ++mf) {
        int r0 = m0 + warp_m * 32 + mf * 16 + grp;
        int r1 = r0 + 8;
#pragma unroll
        for (int nf = 0; nf < 4; ++nf) {
            int c = n0 + warp_n * 32 + nf * 8 + tig * 2;
            if (r0 < M)
                *(float2*)&C[(size_t)r0 * ldc + c] = make_float2(acc[mf][nf][0], acc[mf][nf][1]);
            if (r1 < M)
                *(float2*)&C[(size_t)r1 * ldc + c] = make_float2(acc[mf][nf][2], acc[mf][nf][3]);
        }
    }

    // ---- fused attention dots: head = n0/32 + warp_n ----
    if (a_src != nullptr) {
        const int head = (n0 >> 5) + warp_n;
#pragma unroll
        for (int mf = 0; mf < 2; ++mf) {
            float ps0 = 0.f, pd0 = 0.f, ps1 = 0.f, pd1 = 0.f;
#pragma unroll
            for (int nf = 0; nf < 4; ++nf) {
                int cl = warp_n * 32 + nf * 8 + tig * 2;
                float w0s = sAs[cl], w1s = sAs[cl + 1];
                float w0d = sAd[cl], w1d = sAd[cl + 1];
                ps0 += acc[mf][nf][0] * w0s + acc[mf][nf][1] * w1s;
                pd0 += acc[mf][nf][0] * w0d + acc[mf][nf][1] * w1d;
                ps1 += acc[mf][nf][2] * w0s + acc[mf][nf][3] * w1s;
                pd1 += acc[mf][nf][2] * w0d + acc[mf][nf][3] * w1d;
            }
#pragma unroll
            for (int off = 1; off <= 2; off <<= 1) {
                ps0 += __shfl_xor_sync(0xffffffffu, ps0, off);
                pd0 += __shfl_xor_sync(0xffffffffu, pd0, off);
                ps1 += __shfl_xor_sync(0xffffffffu, ps1, off);
                pd1 += __shfl_xor_sync(0xffffffffu, pd1, off);
            }
            if (tig == 0) {
                int r0 = m0 + warp_m * 32 + mf * 16 + grp;
                int r1 = r0 + 8;
                if (r0 < M) { g_asrc[r0 * 8 + head] = ps0; g_adst[r0 * 8 + head] = pd0; }
                if (r1 < M) { g_asrc[r1 * 8 + head] = ps1; g_adst[r1 * 8 + head] = pd1; }
            }
        }
    }
}

// ---------------- CSR build ----------------
__global__ __launch_bounds__(256) void zero_cnt_kernel()
{
    int i = blockIdx.x * blockDim.x + threadIdx.x;
    if (i < N_NODES) g_cnt[i] = 0;
}
__global__ __launch_bounds__(256) void count_kernel(const int* __restrict__ ei)
{
    int e = blockIdx.x * blockDim.x + threadIdx.x;
    if (e < N_EDGES) atomicAdd(&g_cnt[ei[N_EDGES + e]], 1);
}
__global__ __launch_bounds__(256) void scan1_kernel()
{
    __shared__ int sh[256];
    int i = blockIdx.x * 256 + threadIdx.x;
    int v = (i < N_NODES) ? g_cnt[i] : 0;
    sh[threadIdx.x] = v;
    __syncthreads();
#pragma unroll
    for (int off = 1; off < 256; off <<= 1) {
        int t = 0;
        if (threadIdx.x >= off) t = sh[threadIdx.x - off];
        __syncthreads();
        if (threadIdx.x >= off) sh[threadIdx.x] += t;
        __syncthreads();
    }
    if (i < N_NODES) g_off[i + 1] = sh[threadIdx.x];
    if (threadIdx.x == 255) g_bsum[blockIdx.x] = sh[255];
    if (i == 0) g_off[0] = 0;
}
__global__ __launch_bounds__(256) void scan2_kernel(int nblocks)
{
    __shared__ int sh[256];
    int t = threadIdx.x;
    int v = (t < nblocks) ? g_bsum[t] : 0;
    sh[t] = v;
    __syncthreads();
#pragma unroll
    for (int off = 1; off < 256; off <<= 1) {
        int u = 0;
        if (t >= off) u = sh[t - off];
        __syncthreads();
        if (t >= off) sh[t] += u;
        __syncthreads();
    }
    if (t < nblocks) g_bsum[t] = sh[t] - v;    // exclusive
}
__global__ __launch_bounds__(256) void scan3_kernel()
{
    int i = blockIdx.x * 256 + threadIdx.x;
    if (i < N_NODES) {
        int v = g_off[i + 1] + g_bsum[blockIdx.x];
        g_off[i + 1] = v;
        if (i + 1 < N_NODES) g_fill[i + 1] = v;   // fill cursor = final offset
        if (i == 0) g_fill[0] = 0;
    }
}
__global__ __launch_bounds__(256) void scatter_kernel(const int* __restrict__ ei)
{
    int e = blockIdx.x * blockDim.x + threadIdx.x;
    if (e >= N_EDGES) return;
    int s = ei[e], d = ei[N_EDGES + e];
    int pos = atomicAdd(&g_fill[d], 1);
    g_csrc[pos] = s;
}

// -------- gather attention: one warp per node, fused softmax+agg+relu ------
__global__ __launch_bounds__(256) void gat_gather_kernel(const float* __restrict__ b)
{
    const int warp = threadIdx.x >> 5, lane = threadIdx.x & 31;
    const int n = blockIdx.x * 8 + warp;
    if (n >= N_NODES) return;
    const unsigned FULL = 0xffffffffu;
    const int h0 = lane >> 3, h1 = 4 + (lane >> 3);

    float myasrc = 0.f, myadst = 0.f;
    if (lane < 8) {
        myasrc = g_asrc[n * 8 + lane];
        myadst = g_adst[n * 8 + lane];
    }
    float4 acc0 = make_float4(0.f, 0.f, 0.f, 0.f);
    float4 acc1 = make_float4(0.f, 0.f, 0.f, 0.f);
    float denom = 0.f;

    const int beg = g_off[n], end = g_off[n + 1];
    for (int i = beg; i < end; ++i) {
        int s = g_csrc[i];
        float w = 0.f;
        if (lane < 8) {
            w = expf(leaky(g_asrc[s * 8 + lane] + myadst));
            denom += w;
        }
        float al0 = __shfl_sync(FULL, w, h0);
        float al1 = __shfl_sync(FULL, w, h1);
        float4 v0 = *(const float4*)&g_h[(size_t)s * 256 + lane * 4];
        float4 v1 = *(const float4*)&g_h[(size_t)s * 256 + 128 + lane * 4];
        acc0.x += al0 * v0.x; acc0.y += al0 * v0.y;
        acc0.z += al0 * v0.z; acc0.w += al0 * v0.w;
        acc1.x += al1 * v1.x; acc1.y += al1 * v1.y;
        acc1.z += al1 * v1.z; acc1.w += al1 * v1.w;
    }
    // self loop
    {
        float w = 0.f;
        if (lane < 8) {
            w = expf(leaky(myasrc + myadst));
            denom += w;
        }
        float al0 = __shfl_sync(FULL, w, h0);
        float al1 = __shfl_sync(FULL, w, h1);
        float4 v0 = *(const float4*)&g_h[(size_t)n * 256 + lane * 4];
        float4 v1 = *(const float4*)&g_h[(size_t)n * 256 + 128 + lane * 4];
        acc0.x += al0 * v0.x; acc0.y += al0 * v0.y;
        acc0.z += al0 * v0.z; acc0.w += al0 * v0.w;
        acc1.x += al1 * v1.x; acc1.y += al1 * v1.y;
        acc1.z += al1 * v1.z; acc1.w += al1 * v1.w;
    }
    float inv0 = 1.f / __shfl_sync(FULL, denom, h0);
    float inv1 = 1.f / __shfl_sync(FULL, denom, h1);
    float4 bb0 = *(const float4*)&b[lane * 4];
    float4 bb1 = *(const float4*)&b[128 + lane * 4];
    float4 o0, o1;
    o0.x = fmaxf(acc0.x * inv0 + bb0.x, 0.f);
    o0.y = fmaxf(acc0.y * inv0 + bb0.y, 0.f);
    o0.z = fmaxf(acc0.z * inv0 + bb0.z, 0.f);
    o0.w = fmaxf(acc0.w * inv0 + bb0.w, 0.f);
    o1.x = fmaxf(acc1.x * inv1 + bb1.x, 0.f);
    o1.y = fmaxf(acc1.y * inv1 + bb1.y, 0.f);
    o1.z = fmaxf(acc1.z * inv1 + bb1.z, 0.f);
    o1.w = fmaxf(acc1.w * inv1 + bb1.w, 0.f);
    *(float4*)&g_x[(size_t)n * 256 + lane * 4] = o0;
    *(float4*)&g_x[(size_t)n * 256 + 128 + lane * 4] = o1;
}

// ---------------- pack Wcat = [Wp1_a | Wp1_b] : [256 x 64] ----------------
__global__ __launch_bounds__(256) void pack_wcat_kernel(const float* __restrict__ Wp1)
{
    int i = blockIdx.x * blockDim.x + threadIdx.x;
    if (i >= 256 * 64) return;
    int k = i >> 6, j = i & 63;
    g_wcat[i] = (j < 32) ? Wp1[k * 32 + j] : Wp1[(256 + k) * 32 + (j - 32)];
}

// ---------------- edge predictor: emb MLP + combine (fp32) ----------------
__global__ __launch_bounds__(128) void edge_pred_kernel(
    const int* __restrict__ ei, const float* __restrict__ edge_attr,
    const float* __restrict__ Wm1, const float* __restrict__ bm1,
    const float* __restrict__ Wm2, const float* __restrict__ bm2,
    const float* __restrict__ Wp1, const float* __restrict__ bp1,
    const float* __restrict__ Wp2, const float* __restrict__ bp2,
    float* __restrict__ out)
{
    __shared__ float sEA[64 * 33];
    __shared__ float sT1[64 * 33];
    __shared__ float sW[3072];          // Wm1 | Wm2 | Wp1_c
    __shared__ int   sRow[64], sCol[64];
    __shared__ float sB[64];            // bm1 | bm2

    const int tid = threadIdx.x;
    const int tx = tid & 7;
    const int ey = tid >> 3;
    const int e0 = blockIdx.x * 64;

    if (tid < 64) {
        sRow[tid] = ei[e0 + tid];
        sCol[tid] = ei[N_EDGES + e0 + tid];
    }
    for (int i = tid; i < 3072; i += 128)
        sW[i] = (i < 1024) ? Wm1[i]
              : (i < 2048) ? Wm2[i - 1024]
                           : Wp1[512 * 32 + (i - 2048)];
    if (tid < 32) { sB[tid] = bm1[tid]; sB[32 + tid] = bm2[tid]; }
    for (int f = tid; f < 64 * 8; f += 128) {
        int e = f >> 3, q = f & 7;
        float4 v = *(const float4*)&edge_attr[(size_t)(e0 + e) * 32 + q * 4];
        float* p = &sEA[e * 33 + q * 4];
        p[0] = v.x; p[1] = v.y; p[2] = v.z; p[3] = v.w;
    }
    __syncthreads();

    // layer 1: T1 = relu(EA @ Wm1 + bm1)
    {
        float acc[4][4];
#pragma unroll
        for (int i = 0; i < 4; ++i)
#pragma unroll
            for (int j = 0; j < 4; ++j) acc[i][j] = 0.f;
#pragma unroll
        for (int k = 0; k < 32; ++k) {
            float4 w = *(const float4*)&sW[k * 32 + tx * 4];
#pragma unroll
            for (int i = 0; i < 4; ++i) {
                float a = sEA[(ey * 4 + i) * 33 + k];
                acc[i][0] += a * w.x; acc[i][1] += a * w.y;
                acc[i][2] += a * w.z; acc[i][3] += a * w.w;
            }
        }
#pragma unroll
        for (int i = 0; i < 4; ++i)
#pragma unroll
            for (int j = 0; j < 4; ++j) {
                float v = acc[i][j] + sB[tx * 4 + j];
                sT1[(ey * 4 + i) * 33 + tx * 4 + j] = v > 0.f ? v : 0.f;
            }
    }
    __syncthreads();
    // layer 2: EMB = relu(T1 @ Wm2 + bm2) -> sEA (reuse)
    {
        float acc[4][4];
#pragma unroll
        for (int i = 0; i < 4; ++i)
#pragma unroll
            for (int j = 0; j < 4; ++j) acc[i][j] = 0.f;
#pragma unroll
        for (int k = 0; k < 32; ++k) {
            float4 w = *(const float4*)&sW[1024 + k * 32 + tx * 4];
#pragma unroll
            for (int i = 0; i < 4; ++i) {
                float a = sT1[(ey * 4 + i) * 33 + k];
                acc[i][0] += a * w.x; acc[i][1] += a * w.y;
                acc[i][2] += a * w.z; acc[i][3] += a * w.w;
            }
        }
        __syncthreads();
#pragma unroll
        for (int i = 0; i < 4; ++i)
#pragma unroll
            for (int j = 0; j < 4; ++j) {
                float v = acc[i][j] + sB[32 + tx * 4 + j];
                sEA[(ey * 4 + i) * 33 + tx * 4 + j] = v > 0.f ? v : 0.f;
            }
    }
    __syncthreads();
    // layer 3: acc = EMB @ Wp1_c
    float acc[4][4];
#pragma unroll
    for (int i = 0; i < 4; ++i)
#pragma unroll
        for (int j = 0; j < 4; ++j) acc[i][j] = 0.f;
#pragma unroll
    for (int k = 0; k < 32; ++k) {
        float4 w = *(const float4*)&sW[2048 + k * 32 + tx * 4];
#pragma unroll
        for (int i = 0; i < 4; ++i) {
            float a = sEA[(ey * 4 + i) * 33 + k];
            acc[i][0] += a * w.x; acc[i][1] += a * w.y;
            acc[i][2] += a * w.z; acc[i][3] += a * w.w;
        }
    }

    // epilogue: pre = acc + P_a[row] + P_b[col] + bp1; out = relu(pre)@Wp2 + bp2
    float4 bp = *(const float4*)&bp1[tx * 4];
    float4 wp = *(const float4*)&Wp2[tx * 4];
    float bias2 = bp2[0];
#pragma unroll
    for (int i = 0; i < 4; ++i) {
        int e = ey * 4 + i;
        int r = sRow[e], c = sCol[e];
        float4 pa = *(const float4*)&g_p[(size_t)r * 64 + tx * 4];
        float4 pb = *(const float4*)&g_p[(size_t)c * 64 + 32 + tx * 4];
        float h0 = acc[i][0] + pa.x + pb.x + bp.x; h0 = h0 > 0.f ? h0 : 0.f;
        float h1 = acc[i][1] + pa.y + pb.y + bp.y; h1 = h1 > 0.f ? h1 : 0.f;
        float h2 = acc[i][2] + pa.z + pb.z + bp.z; h2 = h2 > 0.f ? h2 : 0.f;
        float h3 = acc[i][3] + pa.w + pb.w + bp.w; h3 = h3 > 0.f ? h3 : 0.f;
        float p = h0 * wp.x + h1 * wp.y + h2 * wp.z + h3 * wp.w;
        p += __shfl_down_sync(0xffffffffu, p, 4, 8);
        p += __shfl_down_sync(0xffffffffu, p, 2, 8);
        p += __shfl_down_sync(0xffffffffu, p, 1, 8);
        if (tx == 0) out[e0 + e] = p + bias2;
    }
}

// ---------------- host ----------------
extern "C" void kernel_launch(void* const* d_in, const int* in_sizes, int n_in,
                              void* d_out, int out_size)
{
    const float* x   = (const float*)d_in[0];
    const int*   ei  = (const int*)d_in[1];
    const float* ea  = (const float*)d_in[2];
    const float* W1  = (const float*)d_in[3];
    const float* as1 = (const float*)d_in[4];
    const float* ad1 = (const float*)d_in[5];
    const float* b1  = (const float*)d_in[6];
    const float* W2  = (const float*)d_in[7];
    const float* as2 = (const float*)d_in[8];
    const float* ad2 = (const float*)d_in[9];
    const float* b2  = (const float*)d_in[10];
    const float* Wm1 = (const float*)d_in[11];
    const float* bm1 = (const float*)d_in[12];
    const float* Wm2 = (const float*)d_in[13];
    const float* bm2 = (const float*)d_in[14];
    const float* Wp1 = (const float*)d_in[15];
    const float* bp1 = (const float*)d_in[16];
    const float* Wp2 = (const float*)d_in[17];
    const float* bp2 = (const float*)d_in[18];
    float* out = (float*)d_out;

    float *ph = nullptr, *px = nullptr, *pw = nullptr, *pp = nullptr;
    cudaGetSymbolAddress((void**)&ph, g_h);
    cudaGetSymbolAddress((void**)&px, g_x);
    cudaGetSymbolAddress((void**)&pw, g_wcat);
    cudaGetSymbolAddress((void**)&pp, g_p);

    const int EB  = (N_EDGES + 255) / 256;
    const int NB  = (N_NODES + 255) / 256;
    const int NWB = (N_NODES + 7) / 8;

    // ---- CSR build (once; reused by both layers) ----
    zero_cnt_kernel<<<NB, 256>>>();
    count_kernel<<<EB, 256>>>(ei);
    scan1_kernel<<<NB, 256>>>();
    scan2_kernel<<<1, 256>>>(NB);
    scan3_kernel<<<NB, 256>>>();
    scatter_kernel<<<EB, 256>>>(ei);

    for (int layer = 0; layer < 2; ++layer) {
        const float* X   = layer ? px : x;
        const int    K   = layer ? 256 : 128;
        const float* W   = layer ? W2 : W1;
        const float* as_ = layer ? as2 : as1;
        const float* ad_ = layer ? ad2 : ad1;
        const float* b_  = layer ? b2 : b1;

        tc_gemm_kernel<<<dim3(391, 4), 256>>>(X, W, ph, N_NODES, K, 256, 256, as_, ad_);
        gat_gather_kernel<<<NWB, 256>>>(b_);
    }
    pack_wcat_kernel<<<64, 256>>>(Wp1);
    tc_gemm_kernel<<<dim3(391, 1), 256>>>(px, pw, pp, N_NODES, 256, 64, 64,
                                          nullptr, nullptr);
    edge_pred_kernel<<<N_EDGES / 64, 128>>>(ei, ea,
                                            Wm1, bm1, Wm2, bm2,
                                            Wp1, bp1, Wp2, bp2, out);
}